// round 6
// baseline (speedup 1.0000x reference)
#include <cuda_runtime.h>

#define BB 8192
#define CC 45
#define LL 21
#define EE 22
#define NNON 23            // 45 - 22
#define LOG2E 1.4426950408889634f

// ---------------- scratch (static device allocations, allowed) ----------------
__device__ float g_gate[BB * CC];
__device__ float g_mean[CC];
__device__ int   g_sel[EE];
__device__ int   g_nonsel[NNON];
__device__ float4 g_scal[EE];   // {a*log2e, cm*log2e, alpha, beta}

__device__ __forceinline__ float ex2f(float v) {
    float r; asm("ex2.approx.f32 %0, %1;" : "=f"(r) : "f"(v)); return r;
}
__device__ __forceinline__ float rcpf(float v) {
    float r; asm("rcp.approx.f32 %0, %1;" : "=f"(r) : "f"(v)); return r;
}

// ---------------- kernel 1: gating (1 warp per batch) ----------------
__global__ __launch_bounds__(256) void gating_kernel(
    const float* __restrict__ x,
    const float* __restrict__ gc_w, const float* __restrict__ gc_b,
    const float* __restrict__ w1, const float* __restrict__ b1,
    const float* __restrict__ w2, const float* __restrict__ b2)
{
    __shared__ float s_x[8][945];
    __shared__ float s_gcw[441];
    __shared__ float s_gcb[21];
    __shared__ float s_w1[1125];
    __shared__ float s_w2[1125];
    __shared__ float s_b1[25];
    __shared__ float s_b2[45];
    __shared__ float s_mx[8][48];
    __shared__ float s_av[8][48];
    __shared__ float s_h1m[8][26];
    __shared__ float s_h1a[8][26];

    const int tid = threadIdx.x;
    for (int i = tid; i < 441; i += 256) s_gcw[i] = gc_w[i];
    for (int i = tid; i < 1125; i += 256) { s_w1[i] = w1[i]; s_w2[i] = w2[i]; }
    if (tid < 21) s_gcb[tid] = gc_b[tid];
    if (tid < 25) s_b1[tid] = b1[tid];
    if (tid < 45) s_b2[tid] = b2[tid];

    const int w = tid >> 5, lane = tid & 31;
    const int b = blockIdx.x * 8 + w;
    const float* xb = x + (size_t)b * 945;
    for (int i = lane; i < 945; i += 32) s_x[w][i] = xb[i];
    __syncthreads();

    // temp[i,o] = gc_w[o,:] . x[b,i,:] + gc_b[o]; pool over o
    for (int i = 0; i < 45; i++) {
        float acc = 0.f;
        if (lane < 21) {
            acc = s_gcb[lane];
            const float* wr = &s_gcw[lane * 21];
            const float* xr = &s_x[w][i * 21];
            #pragma unroll
            for (int l = 0; l < 21; l++) acc = fmaf(wr[l], xr[l], acc);
        }
        float m = (lane < 21) ? acc : -1e30f;
        float s = (lane < 21) ? acc : 0.f;
        #pragma unroll
        for (int off = 16; off; off >>= 1) {
            m = fmaxf(m, __shfl_xor_sync(0xffffffffu, m, off));
            s += __shfl_xor_sync(0xffffffffu, s, off);
        }
        if (lane == 0) { s_mx[w][i] = m; s_av[w][i] = s * (1.0f / 21.0f); }
    }
    __syncwarp();

    // MLP layer 1 (45 -> 25), applied to mx and av
    if (lane < 25) {
        float am = s_b1[lane], aa = am;
        const float* wr = &s_w1[lane * 45];
        #pragma unroll
        for (int i = 0; i < 45; i++) {
            am = fmaf(wr[i], s_mx[w][i], am);
            aa = fmaf(wr[i], s_av[w][i], aa);
        }
        s_h1m[w][lane] = tanhf(am);
        s_h1a[w][lane] = tanhf(aa);
    }
    __syncwarp();

    // MLP layer 2 (25 -> 45): each lane covers j=lane and j=lane+32
    float lg0, lg1 = -1e30f;
    {
        const int j = lane;
        float am = s_b2[j], aa = am;
        const float* wr = &s_w2[j * 25];
        #pragma unroll
        for (int k = 0; k < 25; k++) {
            am = fmaf(wr[k], s_h1m[w][k], am);
            aa = fmaf(wr[k], s_h1a[w][k], aa);
        }
        lg0 = tanhf(am) + tanhf(aa);
    }
    if (lane < 13) {
        const int j = lane + 32;
        float am = s_b2[j], aa = am;
        const float* wr = &s_w2[j * 25];
        #pragma unroll
        for (int k = 0; k < 25; k++) {
            am = fmaf(wr[k], s_h1m[w][k], am);
            aa = fmaf(wr[k], s_h1a[w][k], aa);
        }
        lg1 = tanhf(am) + tanhf(aa);
    }

    // softmax over 45 logits
    float M = fmaxf(lg0, lg1);
    #pragma unroll
    for (int off = 16; off; off >>= 1)
        M = fmaxf(M, __shfl_xor_sync(0xffffffffu, M, off));
    float e0 = __expf(lg0 - M);
    float e1 = (lane < 13) ? __expf(lg1 - M) : 0.f;
    float S = e0 + e1;
    #pragma unroll
    for (int off = 16; off; off >>= 1)
        S += __shfl_xor_sync(0xffffffffu, S, off);
    const float inv = 1.0f / S;
    g_gate[(size_t)b * 45 + lane] = e0 * inv;
    if (lane < 13) g_gate[(size_t)b * 45 + lane + 32] = e1 * inv;
}

// ---------------- kernel 2: deterministic per-channel mean over batch ----------------
__global__ void mean_kernel()
{
    const int ch = blockIdx.x;
    const int tid = threadIdx.x;
    float s = 0.f;
    for (int b = tid; b < BB; b += 256) s += g_gate[(size_t)b * 45 + ch];
    __shared__ float sm[256];
    sm[tid] = s;
    __syncthreads();
    for (int off = 128; off; off >>= 1) {
        if (tid < off) sm[tid] += sm[tid + off];
        __syncthreads();
    }
    if (tid == 0) g_mean[ch] = sm[0] * (1.0f / (float)BB);
}

// ---------------- kernel 3: top-22 selection + expert scalar precompute ----------------
__global__ void topk_kernel(
    const float* __restrict__ wq, const float* __restrict__ bq,
    const float* __restrict__ wk, const float* __restrict__ bk,
    const float* __restrict__ wv, const float* __restrict__ bv,
    const float* __restrict__ wo, const float* __restrict__ bo)
{
    const int tid = threadIdx.x;
    if (tid == 0) {
        float m[45]; bool used[45];
        for (int c = 0; c < 45; c++) { m[c] = g_mean[c]; used[c] = false; }
        int idx[EE];
        for (int r = 0; r < EE; r++) {
            float best = -1e30f; int bi = 0;
            for (int c = 0; c < 45; c++)
                if (!used[c] && m[c] > best) { best = m[c]; bi = c; }
            used[bi] = true; idx[r] = bi;
        }
        // sort ascending (insertion)
        for (int i = 1; i < EE; i++) {
            int v = idx[i], j = i - 1;
            while (j >= 0 && idx[j] > v) { idx[j + 1] = idx[j]; j--; }
            idx[j + 1] = v;
        }
        for (int r = 0; r < EE; r++) g_sel[r] = idx[r];
        int p = 0;
        for (int c = 0; c < 45; c++) if (!used[c]) g_nonsel[p++] = c;
    }
    if (tid >= 32 && tid < 32 + EE) {
        const int e = tid - 32;
        float a = 0.f, cm = 0.f, Al = 0.f, Be = bo[e];
        #pragma unroll
        for (int c = 0; c < 21; c++) {
            a  = fmaf(wq[e * 21 + c], wk[e * 21 + c], a);
            cm = fmaf(bq[e * 21 + c], wk[e * 21 + c], cm);
            Al = fmaf(wo[e * 21 + c], wv[e * 21 + c], Al);
            Be = fmaf(wo[e * 21 + c], bv[e * 21 + c], Be);
        }
        g_scal[e] = make_float4(a * LOG2E, cm * LOG2E, Al, Be);
    }
}

// ---------------- kernel 4: collapsed attention + routing + output ----------------
__global__ __launch_bounds__(512) void attn_kernel(
    const float* __restrict__ x,
    float* __restrict__ outG, float* __restrict__ outA)
{
    __shared__ float sxs[EE][21];
    __shared__ float sg[EE][21];

    const int tid = threadIdx.x;
    const int b = blockIdx.x;
    const int e = tid / 21;
    const int l = tid - e * 21;
    const bool act = (tid < EE * 21);

    float4 sc = make_float4(0.f, 0.f, 0.f, 0.f);
    int ch = 0;
    float xl = 0.f, gate_v = 0.f;
    if (act) {
        ch = g_sel[e];
        sc = g_scal[e];
        xl = x[(size_t)b * 945 + ch * 21 + l];
        sxs[e][l] = xl;
        sg[e][l] = ex2f(sc.y * xl);           // exp(cm * x_m), row-const terms cancel
        gate_v = g_gate[(size_t)b * 45 + ch];
    }
    __syncthreads();

    if (act) {
        const float u = sc.x * xl;            // a*log2e * x_l
        float num = 0.f, den = 0.f;
        #pragma unroll
        for (int m = 0; m < 21; m++) {
            const float xm = sxs[e][m];
            const float t = ex2f(u * xm) * sg[e][m];
            den += t;
            num = fmaf(t, xm, num);
        }
        const float s1 = num * rcpf(den);
        const float y = fmaf(sc.z, s1, sc.w); // alpha*s1 + beta
        const float Av = y * gate_v;
        const size_t off = (size_t)b * 945 + ch * 21 + l;
        outA[off] = Av;
        outG[off] = xl * Av;
    }

    // zero the 23 unselected channels (d_out is poisoned)
    for (int idx = tid; idx < NNON * 21; idx += 512) {
        const int ci = idx / 21;
        const int ll = idx - ci * 21;
        const int c = g_nonsel[ci];
        const size_t off = (size_t)b * 945 + c * 21 + ll;
        outA[off] = 0.f;
        outG[off] = 0.f;
    }
}

// ---------------- launch ----------------
extern "C" void kernel_launch(void* const* d_in, const int* in_sizes, int n_in,
                              void* d_out, int out_size)
{
    const float* x    = (const float*)d_in[0];
    const float* gc_w = (const float*)d_in[1];
    const float* gc_b = (const float*)d_in[2];
    const float* w1   = (const float*)d_in[3];
    const float* b1   = (const float*)d_in[4];
    const float* w2   = (const float*)d_in[5];
    const float* b2   = (const float*)d_in[6];
    const float* wq   = (const float*)d_in[7];
    const float* bq   = (const float*)d_in[8];
    const float* wk   = (const float*)d_in[9];
    const float* bk   = (const float*)d_in[10];
    const float* wv   = (const float*)d_in[11];
    const float* bv   = (const float*)d_in[12];
    const float* wo   = (const float*)d_in[13];
    const float* bo   = (const float*)d_in[14];

    float* G = (float*)d_out;
    float* A = G + (size_t)BB * CC * LL;   // outputs concatenated: G then A_flat

    gating_kernel<<<BB / 8, 256>>>(x, gc_w, gc_b, w1, b1, w2, b2);
    mean_kernel<<<CC, 256>>>();
    topk_kernel<<<1, 64>>>(wq, bq, wk, bk, wv, bv, wo, bo);
    attn_kernel<<<BB, 512>>>(x, G, A);
}

// round 7
// speedup vs baseline: 1.4641x; 1.4641x over previous
#include <cuda_runtime.h>

#define BB 8192
#define CC 45
#define LL 21
#define EE 22
#define NNON 23            // 45 - 22
#define LOG2E 1.4426950408889634f
#define NBLK 1024          // gating blocks (8 batches each)

// ---------------- scratch (__device__ globals, allowed) ----------------
__device__ float g_gate[BB * CC];
__device__ float g_partial[NBLK * CC];
__device__ float g_mean[CC];
__device__ int   g_sel[EE];
__device__ int   g_nonsel[NNON];
__device__ float4 g_scal[EE];   // {a*log2e, cm*log2e, alpha, beta}

__device__ __forceinline__ float ex2f(float v) {
    float r; asm("ex2.approx.f32 %0, %1;" : "=f"(r) : "f"(v)); return r;
}
__device__ __forceinline__ float rcpf(float v) {
    float r; asm("rcp.approx.f32 %0, %1;" : "=f"(r) : "f"(v)); return r;
}

// ---------------- kernel 1: gating, thread-per-(batch,channel) ----------------
// blockDim = 384, 8 batches per block (360 active compute threads)
__global__ __launch_bounds__(384) void gating_kernel(
    const float* __restrict__ x,
    const float* __restrict__ gc_w, const float* __restrict__ gc_b,
    const float* __restrict__ w1, const float* __restrict__ b1,
    const float* __restrict__ w2, const float* __restrict__ b2)
{
    __shared__ float s_x[8][945];
    __shared__ __align__(16) float s_gcw[21][24];   // padded rows, 96B stride (16B aligned)
    __shared__ float s_wavg[22];                    // [21] = mean(gc_b)
    __shared__ float s_gcb[21];
    __shared__ float s_w1[1125];
    __shared__ float s_w2[1125];
    __shared__ float s_b1[25];
    __shared__ float s_b2[45];
    __shared__ float s_mx[8][45];
    __shared__ float s_av[8][45];
    __shared__ float s_h1m[8][25];
    __shared__ float s_h1a[8][25];
    __shared__ float s_lg[8][45];
    __shared__ float s_g[8][45];
    __shared__ float s_red[8][2];                   // {M, invS}

    const int tid = threadIdx.x;

    // ---- cooperative loads ----
    {
        const float* xb = x + (size_t)blockIdx.x * 8 * 945;
        float* sx = &s_x[0][0];
        for (int i = tid; i < 8 * 945; i += 384) sx[i] = xb[i];
    }
    for (int i = tid; i < 441; i += 384) {
        int o = i / 21, l = i - o * 21;
        s_gcw[o][l] = gc_w[i];
    }
    for (int i = tid; i < 1125; i += 384) { s_w1[i] = w1[i]; s_w2[i] = w2[i]; }
    if (tid < 21) s_gcb[tid] = gc_b[tid];
    if (tid < 25) s_b1[tid] = b1[tid];
    if (tid < 45) s_b2[tid] = b2[tid];
    __syncthreads();

    // averaged conv weights (avg-pool collapses to one dot)
    if (tid < 21) {
        float s = 0.f;
        #pragma unroll
        for (int o = 0; o < 21; o++) s += s_gcw[o][tid];
        s_wavg[tid] = s * (1.0f / 21.0f);
    }
    if (tid == 32) {
        float s = 0.f;
        #pragma unroll
        for (int o = 0; o < 21; o++) s += s_gcb[o];
        s_wavg[21] = s * (1.0f / 21.0f);
    }
    __syncthreads();

    const int w = tid / 45;
    const int i = tid - w * 45;
    const bool act = (tid < 360);

    // ---- conv + pooling ----
    if (act) {
        float xr[21];
        const float* xrow = &s_x[w][i * 21];
        #pragma unroll
        for (int l = 0; l < 21; l++) xr[l] = xrow[l];

        float mx = -1e30f;
        for (int o = 0; o < 21; o++) {
            const float4* wr4 = (const float4*)&s_gcw[o][0];
            float acc = s_gcb[o];
            #pragma unroll
            for (int q = 0; q < 5; q++) {
                float4 wv = wr4[q];
                acc = fmaf(wv.x, xr[4 * q + 0], acc);
                acc = fmaf(wv.y, xr[4 * q + 1], acc);
                acc = fmaf(wv.z, xr[4 * q + 2], acc);
                acc = fmaf(wv.w, xr[4 * q + 3], acc);
            }
            acc = fmaf(s_gcw[o][20], xr[20], acc);
            mx = fmaxf(mx, acc);
        }
        float av = s_wavg[21];
        #pragma unroll
        for (int l = 0; l < 21; l++) av = fmaf(s_wavg[l], xr[l], av);
        s_mx[w][i] = mx;
        s_av[w][i] = av;
    }
    __syncthreads();

    // ---- MLP layer 1 (45->25) on both mx and av ----
    if (tid < 200) {
        const int w1b = tid / 25, j = tid - w1b * 25;
        float am = s_b1[j], aa = am;
        const float* wr = &s_w1[j * 45];
        #pragma unroll
        for (int k = 0; k < 45; k++) {
            const float wv = wr[k];
            am = fmaf(wv, s_mx[w1b][k], am);
            aa = fmaf(wv, s_av[w1b][k], aa);
        }
        s_h1m[w1b][j] = tanhf(am);
        s_h1a[w1b][j] = tanhf(aa);
    }
    __syncthreads();

    // ---- MLP layer 2 (25->45), logits ----
    if (act) {
        float am = s_b2[i], aa = am;
        const float* wr = &s_w2[i * 25];
        #pragma unroll
        for (int k = 0; k < 25; k++) {
            const float wv = wr[k];
            am = fmaf(wv, s_h1m[w][k], am);
            aa = fmaf(wv, s_h1a[w][k], aa);
        }
        s_lg[w][i] = tanhf(am) + tanhf(aa);
    }
    __syncthreads();

    // ---- softmax over 45 (per-batch) ----
    if (tid < 8) {
        float M = -1e30f;
        #pragma unroll
        for (int j = 0; j < 45; j++) M = fmaxf(M, s_lg[tid][j]);
        s_red[tid][0] = M;
    }
    __syncthreads();
    if (act) s_g[w][i] = __expf(s_lg[w][i] - s_red[w][0]);
    __syncthreads();
    if (tid < 8) {
        float S = 0.f;
        #pragma unroll
        for (int j = 0; j < 45; j++) S += s_g[tid][j];
        s_red[tid][1] = 1.0f / S;
    }
    __syncthreads();
    if (act) {
        const float g = s_g[w][i] * s_red[w][1];
        s_g[w][i] = g;
        g_gate[((size_t)blockIdx.x * 8 + w) * 45 + i] = g;
    }
    __syncthreads();
    // per-block partial sums for the batch mean (deterministic)
    if (tid < 45) {
        float p = 0.f;
        #pragma unroll
        for (int ww = 0; ww < 8; ww++) p += s_g[ww][tid];
        g_partial[blockIdx.x * 45 + tid] = p;
    }
}

// ---------------- kernel 2: fused mean + top-22 + expert scalars ----------------
__global__ __launch_bounds__(1024) void meantopk_kernel(
    const float* __restrict__ wq, const float* __restrict__ bq,
    const float* __restrict__ wk, const float* __restrict__ bk,
    const float* __restrict__ wv, const float* __restrict__ bv,
    const float* __restrict__ wo, const float* __restrict__ bo)
{
    const int tid = threadIdx.x;
    const int wid = tid >> 5, lane = tid & 31;

    // deterministic column reduce of g_partial[1024][45]
    for (int ch = wid; ch < 45; ch += 32) {
        float s = 0.f;
        for (int i = lane; i < NBLK; i += 32) s += g_partial[i * 45 + ch];
        #pragma unroll
        for (int off = 16; off; off >>= 1) s += __shfl_xor_sync(0xffffffffu, s, off);
        if (lane == 0) g_mean[ch] = s;   // scale irrelevant for top-k
    }
    __syncthreads();

    if (tid == 0) {
        float m[45]; bool used[45];
        for (int c = 0; c < 45; c++) { m[c] = g_mean[c]; used[c] = false; }
        int idx[EE];
        for (int r = 0; r < EE; r++) {
            float best = -1e30f; int bi = 0;
            for (int c = 0; c < 45; c++)
                if (!used[c] && m[c] > best) { best = m[c]; bi = c; }
            used[bi] = true; idx[r] = bi;
        }
        for (int a = 1; a < EE; a++) {            // sort ascending
            int v = idx[a], j = a - 1;
            while (j >= 0 && idx[j] > v) { idx[j + 1] = idx[j]; j--; }
            idx[j + 1] = v;
        }
        for (int r = 0; r < EE; r++) g_sel[r] = idx[r];
        int p = 0;
        for (int c = 0; c < 45; c++) if (!used[c]) g_nonsel[p++] = c;
    }
    if (tid >= 32 && tid < 32 + EE) {
        const int e = tid - 32;
        float a = 0.f, cm = 0.f, Al = 0.f, Be = bo[e];
        #pragma unroll
        for (int c = 0; c < 21; c++) {
            a  = fmaf(wq[e * 21 + c], wk[e * 21 + c], a);
            cm = fmaf(bq[e * 21 + c], wk[e * 21 + c], cm);
            Al = fmaf(wo[e * 21 + c], wv[e * 21 + c], Al);
            Be = fmaf(wo[e * 21 + c], bv[e * 21 + c], Be);
        }
        g_scal[e] = make_float4(a * LOG2E, cm * LOG2E, Al, Be);
    }
}

// ---------------- kernel 3: collapsed attention + routing + output ----------------
// t_lm = exp(a*xl*xm + cm*xm) = ex2((aL2E*xl + cmL2E)*xm)  -> per-thread constant v
__global__ __launch_bounds__(512) void attn_kernel(
    const float* __restrict__ x,
    float* __restrict__ outG, float* __restrict__ outA)
{
    __shared__ float sxs[EE * 21];
    __shared__ float4 s_scal[EE];
    __shared__ int   s_sel[EE];
    __shared__ int   s_nonsel[NNON];

    const int tid = threadIdx.x;
    const int b = blockIdx.x;
    const int e = tid / 21;
    const int l = tid - e * 21;
    const bool act = (tid < EE * 21);

    if (tid < EE) { s_sel[tid] = g_sel[tid]; s_scal[tid] = g_scal[tid]; }
    if (tid >= 32 && tid < 32 + NNON) s_nonsel[tid - 32] = g_nonsel[tid - 32];
    __syncthreads();

    float xl = 0.f, gate_v = 0.f, v = 0.f;
    float4 sc = make_float4(0.f, 0.f, 0.f, 0.f);
    size_t off = 0;
    if (act) {
        const int ch = s_sel[e];
        sc = s_scal[e];
        off = (size_t)b * 945 + ch * 21 + l;
        xl = x[off];
        sxs[tid] = xl;
        gate_v = g_gate[(size_t)b * 45 + ch];
        v = fmaf(sc.x, xl, sc.y);               // aL2E*xl + cmL2E
    }
    __syncthreads();

    if (act) {
        const float* row = &sxs[e * 21];
        float num = 0.f, den = 0.f;
        #pragma unroll
        for (int m = 0; m < 21; m++) {
            const float xm = row[m];
            const float t = ex2f(v * xm);
            den += t;
            num = fmaf(t, xm, num);
        }
        const float y = fmaf(sc.z, num * rcpf(den), sc.w);  // alpha*s1 + beta
        const float Av = y * gate_v;
        outA[off] = Av;
        outG[off] = xl * Av;
    }

    // zero the 23 unselected channels (d_out is poisoned)
    if (tid < NNON * 21) {
        const int ci = tid / 21;
        const int ll = tid - ci * 21;
        const size_t o2 = (size_t)b * 945 + s_nonsel[ci] * 21 + ll;
        outA[o2] = 0.f;
        outG[o2] = 0.f;
    }
}

// ---------------- launch ----------------
extern "C" void kernel_launch(void* const* d_in, const int* in_sizes, int n_in,
                              void* d_out, int out_size)
{
    const float* x    = (const float*)d_in[0];
    const float* gc_w = (const float*)d_in[1];
    const float* gc_b = (const float*)d_in[2];
    const float* w1   = (const float*)d_in[3];
    const float* b1   = (const float*)d_in[4];
    const float* w2   = (const float*)d_in[5];
    const float* b2   = (const float*)d_in[6];
    const float* wq   = (const float*)d_in[7];
    const float* bq   = (const float*)d_in[8];
    const float* wk   = (const float*)d_in[9];
    const float* bk   = (const float*)d_in[10];
    const float* wv   = (const float*)d_in[11];
    const float* bv   = (const float*)d_in[12];
    const float* wo   = (const float*)d_in[13];
    const float* bo   = (const float*)d_in[14];

    float* G = (float*)d_out;
    float* A = G + (size_t)BB * CC * LL;   // outputs concatenated: G then A_flat

    gating_kernel<<<NBLK, 384>>>(x, gc_w, gc_b, w1, b1, w2, b2);
    meantopk_kernel<<<1, 1024>>>(wq, bq, wk, bk, wv, bv, wo, bo);
    attn_kernel<<<BB, 512>>>(x, G, A);
}

// round 8
// speedup vs baseline: 1.7989x; 1.2287x over previous
#include <cuda_runtime.h>

#define BB 8192
#define CC 45
#define LL 21
#define EE 22
#define NNON 23            // 45 - 22
#define LOG2E 1.4426950408889634f
#define NBLK 1024          // gating blocks (8 batches each)
#define AB 4               // attn batches per block

// ---------------- scratch (__device__ globals, allowed) ----------------
__device__ float g_gate[BB * CC];
__device__ float g_partial[NBLK * CC];
__device__ float g_mean[CC];
__device__ int   g_sel[EE];
__device__ int   g_nonsel[NNON];
__device__ float4 g_scal[EE];   // {a*log2e, cm*log2e, alpha, beta}

__device__ __forceinline__ float ex2f(float v) {
    float r; asm("ex2.approx.f32 %0, %1;" : "=f"(r) : "f"(v)); return r;
}
__device__ __forceinline__ float rcpf(float v) {
    float r; asm("rcp.approx.f32 %0, %1;" : "=f"(r) : "f"(v)); return r;
}

// ---------------- kernel 1: gating, 2 batches per thread ----------------
// block = 192 threads; 8 batches per block; conv threads: tid<180 = (w0 in 0..3, i in 0..44),
// each handles batches w0 and w0+4 (weight loads amortized over 2 FMA chains).
__global__ __launch_bounds__(192) void gating_kernel(
    const float* __restrict__ x,
    const float* __restrict__ gc_w, const float* __restrict__ gc_b,
    const float* __restrict__ w1, const float* __restrict__ b1,
    const float* __restrict__ w2, const float* __restrict__ b2)
{
    __shared__ float s_x[8][945];
    __shared__ __align__(16) float s_gcw[21][24];   // 96B rows, 16B aligned
    __shared__ float s_gcb[21];
    __shared__ float s_w1[1125];
    __shared__ float s_w2[1125];
    __shared__ float s_b1[25];
    __shared__ float s_b2[45];
    __shared__ float s_mx[8][45];    // conv max -> later reused for logits
    __shared__ float s_av[8][48];    // conv avg -> later reused for gate values
    __shared__ float s_h1m[8][25];
    __shared__ float s_h1a[8][25];

    const int tid = threadIdx.x;

    // ---- cooperative loads ----
    {
        const float4* xb = (const float4*)(x + (size_t)blockIdx.x * 8 * 945);
        float4* sx = (float4*)&s_x[0][0];
        #pragma unroll
        for (int i = tid; i < 8 * 945 / 4; i += 192) sx[i] = xb[i];
    }
    for (int i = tid; i < 441; i += 192) {
        int o = i / 21, l = i - o * 21;
        s_gcw[o][l] = gc_w[i];
    }
    for (int i = tid; i < 1125; i += 192) { s_w1[i] = w1[i]; s_w2[i] = w2[i]; }
    if (tid < 21) s_gcb[tid] = gc_b[tid];
    if (tid < 25) s_b1[tid] = b1[tid];
    if (tid < 45) s_b2[tid] = b2[tid];
    __syncthreads();

    const int w0 = tid / 45;            // 0..3 (for tid<180)
    const int i  = tid - w0 * 45;
    const bool act = (tid < 180);

    // ---- conv + max/avg pooling, 2 batches per thread ----
    if (act) {
        float xa[21], xb[21];
        const float* xra = &s_x[w0][i * 21];
        const float* xrb = &s_x[w0 + 4][i * 21];
        #pragma unroll
        for (int l = 0; l < 21; l++) { xa[l] = xra[l]; xb[l] = xrb[l]; }

        float mxA = -1e30f, mxB = -1e30f, sA = 0.f, sB = 0.f;
        #pragma unroll 7
        for (int o = 0; o < 21; o++) {
            const float4* wr4 = (const float4*)&s_gcw[o][0];
            float accA = s_gcb[o], accB = accA;
            #pragma unroll
            for (int q = 0; q < 5; q++) {
                float4 wv = wr4[q];
                accA = fmaf(wv.x, xa[4 * q + 0], accA);
                accB = fmaf(wv.x, xb[4 * q + 0], accB);
                accA = fmaf(wv.y, xa[4 * q + 1], accA);
                accB = fmaf(wv.y, xb[4 * q + 1], accB);
                accA = fmaf(wv.z, xa[4 * q + 2], accA);
                accB = fmaf(wv.z, xb[4 * q + 2], accB);
                accA = fmaf(wv.w, xa[4 * q + 3], accA);
                accB = fmaf(wv.w, xb[4 * q + 3], accB);
            }
            const float w20 = s_gcw[o][20];
            accA = fmaf(w20, xa[20], accA);
            accB = fmaf(w20, xb[20], accB);
            mxA = fmaxf(mxA, accA); sA += accA;
            mxB = fmaxf(mxB, accB); sB += accB;
        }
        s_mx[w0][i] = mxA;  s_av[w0][i] = sA * (1.0f / 21.0f);
        s_mx[w0 + 4][i] = mxB;  s_av[w0 + 4][i] = sB * (1.0f / 21.0f);
    }
    __syncthreads();

    // ---- MLP layer 1 (45->25), 2 batches per thread ----
    if (tid < 100) {
        const int p = tid / 25, j = tid - p * 25;  // batches p, p+4
        float amA = s_b1[j], aaA = amA, amB = amA, aaB = amA;
        const float* wr = &s_w1[j * 45];
        #pragma unroll
        for (int k = 0; k < 45; k++) {
            const float wv = wr[k];
            amA = fmaf(wv, s_mx[p][k], amA);
            aaA = fmaf(wv, s_av[p][k], aaA);
            amB = fmaf(wv, s_mx[p + 4][k], amB);
            aaB = fmaf(wv, s_av[p + 4][k], aaB);
        }
        s_h1m[p][j] = tanhf(amA);  s_h1a[p][j] = tanhf(aaA);
        s_h1m[p + 4][j] = tanhf(amB);  s_h1a[p + 4][j] = tanhf(aaB);
    }
    __syncthreads();

    // ---- MLP layer 2 (25->45), logits -> reuse s_mx ----
    if (act) {
        float amA = s_b2[i], aaA = amA, amB = amA, aaB = amA;
        const float* wr = &s_w2[i * 25];
        #pragma unroll
        for (int k = 0; k < 25; k++) {
            const float wv = wr[k];
            amA = fmaf(wv, s_h1m[w0][k], amA);
            aaA = fmaf(wv, s_h1a[w0][k], aaA);
            amB = fmaf(wv, s_h1m[w0 + 4][k], amB);
            aaB = fmaf(wv, s_h1a[w0 + 4][k], aaB);
        }
        s_mx[w0][i] = tanhf(amA) + tanhf(aaA);
        s_mx[w0 + 4][i] = tanhf(amB) + tanhf(aaB);
    }
    __syncthreads();

    // ---- softmax over 45, warp per batch (6 warps cover 8 batches) ----
    {
        const int wid = tid >> 5, lane = tid & 31;
        for (int bb = wid; bb < 8; bb += 6) {
            float v0 = s_mx[bb][lane];
            float v1 = (lane < 13) ? s_mx[bb][lane + 32] : -1e30f;
            float M = fmaxf(v0, v1);
            #pragma unroll
            for (int off = 16; off; off >>= 1)
                M = fmaxf(M, __shfl_xor_sync(0xffffffffu, M, off));
            float e0 = __expf(v0 - M);
            float e1 = (lane < 13) ? __expf(v1 - M) : 0.f;
            float S = e0 + e1;
            #pragma unroll
            for (int off = 16; off; off >>= 1)
                S += __shfl_xor_sync(0xffffffffu, S, off);
            const float inv = 1.0f / S;
            const float g0 = e0 * inv, g1 = e1 * inv;
            s_av[bb][lane] = g0;
            const size_t gb = ((size_t)blockIdx.x * 8 + bb) * 45;
            g_gate[gb + lane] = g0;
            if (lane < 13) { s_av[bb][lane + 32] = g1; g_gate[gb + lane + 32] = g1; }
        }
    }
    __syncthreads();

    // per-block partial sums for the batch mean (deterministic)
    if (tid < 45) {
        float p = 0.f;
        #pragma unroll
        for (int ww = 0; ww < 8; ww++) p += s_av[ww][tid];
        g_partial[blockIdx.x * 45 + tid] = p;
    }
}

// ---------------- kernel 2: fused mean + top-22 + expert scalars ----------------
__global__ __launch_bounds__(1024) void meantopk_kernel(
    const float* __restrict__ wq, const float* __restrict__ bq,
    const float* __restrict__ wk, const float* __restrict__ bk,
    const float* __restrict__ wv, const float* __restrict__ bv,
    const float* __restrict__ wo, const float* __restrict__ bo)
{
    const int tid = threadIdx.x;
    const int wid = tid >> 5, lane = tid & 31;

    // deterministic column reduce of g_partial[1024][45]
    for (int ch = wid; ch < 45; ch += 32) {
        float s = 0.f;
        for (int i = lane; i < NBLK; i += 32) s += g_partial[i * 45 + ch];
        #pragma unroll
        for (int off = 16; off; off >>= 1) s += __shfl_xor_sync(0xffffffffu, s, off);
        if (lane == 0) g_mean[ch] = s;   // scale irrelevant for top-k
    }
    __syncthreads();

    if (tid == 0) {
        float m[45]; bool used[45];
        for (int c = 0; c < 45; c++) { m[c] = g_mean[c]; used[c] = false; }
        int idx[EE];
        for (int r = 0; r < EE; r++) {
            float best = -1e30f; int bi = 0;
            for (int c = 0; c < 45; c++)
                if (!used[c] && m[c] > best) { best = m[c]; bi = c; }
            used[bi] = true; idx[r] = bi;
        }
        for (int a = 1; a < EE; a++) {            // sort ascending
            int v = idx[a], j = a - 1;
            while (j >= 0 && idx[j] > v) { idx[j + 1] = idx[j]; j--; }
            idx[j + 1] = v;
        }
        for (int r = 0; r < EE; r++) g_sel[r] = idx[r];
        int p = 0;
        for (int c = 0; c < 45; c++) if (!used[c]) g_nonsel[p++] = c;
    }
    if (tid >= 32 && tid < 32 + EE) {
        const int e = tid - 32;
        float a = 0.f, cm = 0.f, Al = 0.f, Be = bo[e];
        #pragma unroll
        for (int c = 0; c < 21; c++) {
            a  = fmaf(wq[e * 21 + c], wk[e * 21 + c], a);
            cm = fmaf(bq[e * 21 + c], wk[e * 21 + c], cm);
            Al = fmaf(wo[e * 21 + c], wv[e * 21 + c], Al);
            Be = fmaf(wo[e * 21 + c], bv[e * 21 + c], Be);
        }
        g_scal[e] = make_float4(a * LOG2E, cm * LOG2E, Al, Be);
    }
}

// ---------------- kernel 3: collapsed attention, thread-per-(batch,expert) ----------------
// x row lives in registers; A staged in smem (zeros included); coalesced float4 output.
__global__ __launch_bounds__(128) void attn_kernel(
    const float* __restrict__ x,
    float* __restrict__ outG, float* __restrict__ outA)
{
    __shared__ float s_x[AB * 945];
    __shared__ float s_A[AB * 945];
    __shared__ float4 s_scal[EE];
    __shared__ int   s_sel[EE];

    const int tid = threadIdx.x;
    const size_t b0 = (size_t)blockIdx.x * AB;

    // stage x + zero A (both float4, fully coalesced)
    {
        const float4* xg = (const float4*)(x + b0 * 945);
        float4* sx4 = (float4*)s_x;
        float4* sA4 = (float4*)s_A;
        const float4 z4 = make_float4(0.f, 0.f, 0.f, 0.f);
        #pragma unroll
        for (int i = tid; i < AB * 945 / 4; i += 128) { sx4[i] = xg[i]; sA4[i] = z4; }
    }
    if (tid < EE) { s_sel[tid] = g_sel[tid]; s_scal[tid] = g_scal[tid]; }
    __syncthreads();

    // rotate compute warps across SMSPs so MUFU load is balanced chip-wide
    const int wid = tid >> 5, lane = tid & 31;
    const int lw = (wid - (blockIdx.x & 3)) & 3;
    const int t = lw * 32 + lane;

    if (t < AB * EE) {
        const int w = t / EE, e = t - w * EE;
        const int ch = s_sel[e];
        const float4 sc = s_scal[e];
        const int base = w * 945 + ch * 21;

        float xr[21];
        #pragma unroll
        for (int l = 0; l < 21; l++) xr[l] = s_x[base + l];

        const float gate_v = g_gate[(b0 + w) * 45 + ch];

        #pragma unroll
        for (int l = 0; l < 21; l++) {
            const float u = fmaf(sc.x, xr[l], sc.y);   // (a*xl + cm) * log2e
            float num = 0.f, den = 0.f;
            #pragma unroll
            for (int m = 0; m < 21; m++) {
                const float tt = ex2f(u * xr[m]);
                den += tt;
                num = fmaf(tt, xr[m], num);
            }
            const float y = fmaf(sc.z, num * rcpf(den), sc.w);
            s_A[base + l] = y * gate_v;
        }
    }
    __syncthreads();

    // coalesced float4 write of A and G = x * A (covers zeroed channels too)
    {
        float4* Ag = (float4*)(outA + b0 * 945);
        float4* Gg = (float4*)(outG + b0 * 945);
        const float4* sx4 = (const float4*)s_x;
        const float4* sA4 = (const float4*)s_A;
        #pragma unroll
        for (int i = tid; i < AB * 945 / 4; i += 128) {
            const float4 a = sA4[i];
            const float4 xv = sx4[i];
            Ag[i] = a;
            Gg[i] = make_float4(a.x * xv.x, a.y * xv.y, a.z * xv.z, a.w * xv.w);
        }
    }
}

// ---------------- launch ----------------
extern "C" void kernel_launch(void* const* d_in, const int* in_sizes, int n_in,
                              void* d_out, int out_size)
{
    const float* x    = (const float*)d_in[0];
    const float* gc_w = (const float*)d_in[1];
    const float* gc_b = (const float*)d_in[2];
    const float* w1   = (const float*)d_in[3];
    const float* b1   = (const float*)d_in[4];
    const float* w2   = (const float*)d_in[5];
    const float* b2   = (const float*)d_in[6];
    const float* wq   = (const float*)d_in[7];
    const float* bq   = (const float*)d_in[8];
    const float* wk   = (const float*)d_in[9];
    const float* bk   = (const float*)d_in[10];
    const float* wv   = (const float*)d_in[11];
    const float* bv   = (const float*)d_in[12];
    const float* wo   = (const float*)d_in[13];
    const float* bo   = (const float*)d_in[14];

    float* G = (float*)d_out;
    float* A = G + (size_t)BB * CC * LL;   // outputs concatenated: G then A_flat

    gating_kernel<<<NBLK, 192>>>(x, gc_w, gc_b, w1, b1, w2, b2);
    meantopk_kernel<<<1, 1024>>>(wq, bq, wk, bk, wv, bv, wo, bo);
    attn_kernel<<<BB / AB, 128>>>(x, G, A);
}

// round 9
// speedup vs baseline: 1.8142x; 1.0085x over previous
#include <cuda_runtime.h>

#define BB 8192
#define CC 45
#define LL 21
#define EE 22
#define NNON 23            // 45 - 22
#define LOG2E 1.4426950408889634f
#define NBLK 1024          // gating blocks (8 batches each)
#define AB 4               // attn batches per block

// ---------------- scratch (__device__ globals, allowed) ----------------
__device__ float g_gate[BB * CC];
__device__ float g_partial[NBLK * CC];
__device__ float g_mean[CC];
__device__ int   g_sel[EE];
__device__ int   g_nonsel[NNON];
__device__ float4 g_scal[EE];   // {a*log2e, cm*log2e, alpha, beta}

__device__ __forceinline__ float ex2f(float v) {
    float r; asm("ex2.approx.f32 %0, %1;" : "=f"(r) : "f"(v)); return r;
}
__device__ __forceinline__ float rcpf(float v) {
    float r; asm("rcp.approx.f32 %0, %1;" : "=f"(r) : "f"(v)); return r;
}

// ---------------- kernel 1: gating, 2 batches per thread ----------------
// block = 192 threads; 8 batches per block; conv threads: tid<180 = (w0 in 0..3, i in 0..44),
// each handles batches w0 and w0+4 (weight loads amortized over 2 FMA chains).
__global__ __launch_bounds__(192) void gating_kernel(
    const float* __restrict__ x,
    const float* __restrict__ gc_w, const float* __restrict__ gc_b,
    const float* __restrict__ w1, const float* __restrict__ b1,
    const float* __restrict__ w2, const float* __restrict__ b2)
{
    __shared__ float s_x[8][945];
    __shared__ __align__(16) float s_gcw[21][24];   // 96B rows, 16B aligned
    __shared__ float s_gcb[21];
    __shared__ float s_w1[1125];
    __shared__ float s_w2[1125];
    __shared__ float s_b1[25];
    __shared__ float s_b2[45];
    __shared__ float s_mx[8][45];    // conv max -> later reused for logits
    __shared__ float s_av[8][48];    // conv avg -> later reused for gate values
    __shared__ float s_h1m[8][25];
    __shared__ float s_h1a[8][25];

    const int tid = threadIdx.x;

    // ---- cooperative loads ----
    {
        const float4* xb = (const float4*)(x + (size_t)blockIdx.x * 8 * 945);
        float4* sx = (float4*)&s_x[0][0];
        #pragma unroll
        for (int i = tid; i < 8 * 945 / 4; i += 192) sx[i] = xb[i];
    }
    for (int i = tid; i < 441; i += 192) {
        int o = i / 21, l = i - o * 21;
        s_gcw[o][l] = gc_w[i];
    }
    for (int i = tid; i < 1125; i += 192) { s_w1[i] = w1[i]; s_w2[i] = w2[i]; }
    if (tid < 21) s_gcb[tid] = gc_b[tid];
    if (tid < 25) s_b1[tid] = b1[tid];
    if (tid < 45) s_b2[tid] = b2[tid];
    __syncthreads();

    const int w0 = tid / 45;            // 0..3 (for tid<180)
    const int i  = tid - w0 * 45;
    const bool act = (tid < 180);

    // ---- conv + max/avg pooling, 2 batches per thread ----
    if (act) {
        float xa[21], xb[21];
        const float* xra = &s_x[w0][i * 21];
        const float* xrb = &s_x[w0 + 4][i * 21];
        #pragma unroll
        for (int l = 0; l < 21; l++) { xa[l] = xra[l]; xb[l] = xrb[l]; }

        float mxA = -1e30f, mxB = -1e30f, sA = 0.f, sB = 0.f;
        #pragma unroll 7
        for (int o = 0; o < 21; o++) {
            const float4* wr4 = (const float4*)&s_gcw[o][0];
            float accA = s_gcb[o], accB = accA;
            #pragma unroll
            for (int q = 0; q < 5; q++) {
                float4 wv = wr4[q];
                accA = fmaf(wv.x, xa[4 * q + 0], accA);
                accB = fmaf(wv.x, xb[4 * q + 0], accB);
                accA = fmaf(wv.y, xa[4 * q + 1], accA);
                accB = fmaf(wv.y, xb[4 * q + 1], accB);
                accA = fmaf(wv.z, xa[4 * q + 2], accA);
                accB = fmaf(wv.z, xb[4 * q + 2], accB);
                accA = fmaf(wv.w, xa[4 * q + 3], accA);
                accB = fmaf(wv.w, xb[4 * q + 3], accB);
            }
            const float w20 = s_gcw[o][20];
            accA = fmaf(w20, xa[20], accA);
            accB = fmaf(w20, xb[20], accB);
            mxA = fmaxf(mxA, accA); sA += accA;
            mxB = fmaxf(mxB, accB); sB += accB;
        }
        s_mx[w0][i] = mxA;  s_av[w0][i] = sA * (1.0f / 21.0f);
        s_mx[w0 + 4][i] = mxB;  s_av[w0 + 4][i] = sB * (1.0f / 21.0f);
    }
    __syncthreads();

    // ---- MLP layer 1 (45->25), 2 batches per thread ----
    if (tid < 100) {
        const int p = tid / 25, j = tid - p * 25;  // batches p, p+4
        float amA = s_b1[j], aaA = amA, amB = amA, aaB = amA;
        const float* wr = &s_w1[j * 45];
        #pragma unroll
        for (int k = 0; k < 45; k++) {
            const float wv = wr[k];
            amA = fmaf(wv, s_mx[p][k], amA);
            aaA = fmaf(wv, s_av[p][k], aaA);
            amB = fmaf(wv, s_mx[p + 4][k], amB);
            aaB = fmaf(wv, s_av[p + 4][k], aaB);
        }
        s_h1m[p][j] = tanhf(amA);  s_h1a[p][j] = tanhf(aaA);
        s_h1m[p + 4][j] = tanhf(amB);  s_h1a[p + 4][j] = tanhf(aaB);
    }
    __syncthreads();

    // ---- MLP layer 2 (25->45), logits -> reuse s_mx ----
    if (act) {
        float amA = s_b2[i], aaA = amA, amB = amA, aaB = amA;
        const float* wr = &s_w2[i * 25];
        #pragma unroll
        for (int k = 0; k < 25; k++) {
            const float wv = wr[k];
            amA = fmaf(wv, s_h1m[w0][k], amA);
            aaA = fmaf(wv, s_h1a[w0][k], aaA);
            amB = fmaf(wv, s_h1m[w0 + 4][k], amB);
            aaB = fmaf(wv, s_h1a[w0 + 4][k], aaB);
        }
        s_mx[w0][i] = tanhf(amA) + tanhf(aaA);
        s_mx[w0 + 4][i] = tanhf(amB) + tanhf(aaB);
    }
    __syncthreads();

    // ---- softmax over 45, warp per batch (6 warps cover 8 batches) ----
    {
        const int wid = tid >> 5, lane = tid & 31;
        for (int bb = wid; bb < 8; bb += 6) {
            float v0 = s_mx[bb][lane];
            float v1 = (lane < 13) ? s_mx[bb][lane + 32] : -1e30f;
            float M = fmaxf(v0, v1);
            #pragma unroll
            for (int off = 16; off; off >>= 1)
                M = fmaxf(M, __shfl_xor_sync(0xffffffffu, M, off));
            float e0 = __expf(v0 - M);
            float e1 = (lane < 13) ? __expf(v1 - M) : 0.f;
            float S = e0 + e1;
            #pragma unroll
            for (int off = 16; off; off >>= 1)
                S += __shfl_xor_sync(0xffffffffu, S, off);
            const float inv = 1.0f / S;
            const float g0 = e0 * inv, g1 = e1 * inv;
            s_av[bb][lane] = g0;
            const size_t gb = ((size_t)blockIdx.x * 8 + bb) * 45;
            g_gate[gb + lane] = g0;
            if (lane < 13) { s_av[bb][lane + 32] = g1; g_gate[gb + lane + 32] = g1; }
        }
    }
    __syncthreads();

    // per-block partial sums for the batch mean (deterministic)
    if (tid < 45) {
        float p = 0.f;
        #pragma unroll
        for (int ww = 0; ww < 8; ww++) p += s_av[ww][tid];
        g_partial[blockIdx.x * 45 + tid] = p;
    }
}

// ---------------- kernel 2: fused mean + top-22 + expert scalars ----------------
__global__ __launch_bounds__(1024) void meantopk_kernel(
    const float* __restrict__ wq, const float* __restrict__ bq,
    const float* __restrict__ wk, const float* __restrict__ bk,
    const float* __restrict__ wv, const float* __restrict__ bv,
    const float* __restrict__ wo, const float* __restrict__ bo)
{
    const int tid = threadIdx.x;
    const int wid = tid >> 5, lane = tid & 31;

    // deterministic column reduce of g_partial[1024][45]
    for (int ch = wid; ch < 45; ch += 32) {
        float s = 0.f;
        for (int i = lane; i < NBLK; i += 32) s += g_partial[i * 45 + ch];
        #pragma unroll
        for (int off = 16; off; off >>= 1) s += __shfl_xor_sync(0xffffffffu, s, off);
        if (lane == 0) g_mean[ch] = s;   // scale irrelevant for top-k
    }
    __syncthreads();

    if (tid == 0) {
        float m[45]; bool used[45];
        for (int c = 0; c < 45; c++) { m[c] = g_mean[c]; used[c] = false; }
        int idx[EE];
        for (int r = 0; r < EE; r++) {
            float best = -1e30f; int bi = 0;
            for (int c = 0; c < 45; c++)
                if (!used[c] && m[c] > best) { best = m[c]; bi = c; }
            used[bi] = true; idx[r] = bi;
        }
        for (int a = 1; a < EE; a++) {            // sort ascending
            int v = idx[a], j = a - 1;
            while (j >= 0 && idx[j] > v) { idx[j + 1] = idx[j]; j--; }
            idx[j + 1] = v;
        }
        for (int r = 0; r < EE; r++) g_sel[r] = idx[r];
        int p = 0;
        for (int c = 0; c < 45; c++) if (!used[c]) g_nonsel[p++] = c;
    }
    if (tid >= 32 && tid < 32 + EE) {
        const int e = tid - 32;
        float a = 0.f, cm = 0.f, Al = 0.f, Be = bo[e];
        #pragma unroll
        for (int c = 0; c < 21; c++) {
            a  = fmaf(wq[e * 21 + c], wk[e * 21 + c], a);
            cm = fmaf(bq[e * 21 + c], wk[e * 21 + c], cm);
            Al = fmaf(wo[e * 21 + c], wv[e * 21 + c], Al);
            Be = fmaf(wo[e * 21 + c], bv[e * 21 + c], Be);
        }
        g_scal[e] = make_float4(a * LOG2E, cm * LOG2E, Al, Be);
    }
}

// ---------------- kernel 3: collapsed attention, thread-per-(batch,expert) ----------------
// x row lives in registers; A staged in smem (zeros included); coalesced float4 output.
__global__ __launch_bounds__(128) void attn_kernel(
    const float* __restrict__ x,
    float* __restrict__ outG, float* __restrict__ outA)
{
    __shared__ float s_x[AB * 945];
    __shared__ float s_A[AB * 945];
    __shared__ float4 s_scal[EE];
    __shared__ int   s_sel[EE];

    const int tid = threadIdx.x;
    const size_t b0 = (size_t)blockIdx.x * AB;

    // stage x + zero A (both float4, fully coalesced)
    {
        const float4* xg = (const float4*)(x + b0 * 945);
        float4* sx4 = (float4*)s_x;
        float4* sA4 = (float4*)s_A;
        const float4 z4 = make_float4(0.f, 0.f, 0.f, 0.f);
        #pragma unroll
        for (int i = tid; i < AB * 945 / 4; i += 128) { sx4[i] = xg[i]; sA4[i] = z4; }
    }
    if (tid < EE) { s_sel[tid] = g_sel[tid]; s_scal[tid] = g_scal[tid]; }
    __syncthreads();

    // rotate compute warps across SMSPs so MUFU load is balanced chip-wide
    const int wid = tid >> 5, lane = tid & 31;
    const int lw = (wid - (blockIdx.x & 3)) & 3;
    const int t = lw * 32 + lane;

    if (t < AB * EE) {
        const int w = t / EE, e = t - w * EE;
        const int ch = s_sel[e];
        const float4 sc = s_scal[e];
        const int base = w * 945 + ch * 21;

        float xr[21];
        #pragma unroll
        for (int l = 0; l < 21; l++) xr[l] = s_x[base + l];

        const float gate_v = g_gate[(b0 + w) * 45 + ch];

        #pragma unroll
        for (int l = 0; l < 21; l++) {
            const float u = fmaf(sc.x, xr[l], sc.y);   // (a*xl + cm) * log2e
            float num = 0.f, den = 0.f;
            #pragma unroll
            for (int m = 0; m < 21; m++) {
                const float tt = ex2f(u * xr[m]);
                den += tt;
                num = fmaf(tt, xr[m], num);
            }
            const float y = fmaf(sc.z, num * rcpf(den), sc.w);
            s_A[base + l] = y * gate_v;
        }
    }
    __syncthreads();

    // coalesced float4 write of A and G = x * A (covers zeroed channels too)
    {
        float4* Ag = (float4*)(outA + b0 * 945);
        float4* Gg = (float4*)(outG + b0 * 945);
        const float4* sx4 = (const float4*)s_x;
        const float4* sA4 = (const float4*)s_A;
        #pragma unroll
        for (int i = tid; i < AB * 945 / 4; i += 128) {
            const float4 a = sA4[i];
            const float4 xv = sx4[i];
            Ag[i] = a;
            Gg[i] = make_float4(a.x * xv.x, a.y * xv.y, a.z * xv.z, a.w * xv.w);
        }
    }
}

// ---------------- launch ----------------
extern "C" void kernel_launch(void* const* d_in, const int* in_sizes, int n_in,
                              void* d_out, int out_size)
{
    const float* x    = (const float*)d_in[0];
    const float* gc_w = (const float*)d_in[1];
    const float* gc_b = (const float*)d_in[2];
    const float* w1   = (const float*)d_in[3];
    const float* b1   = (const float*)d_in[4];
    const float* w2   = (const float*)d_in[5];
    const float* b2   = (const float*)d_in[6];
    const float* wq   = (const float*)d_in[7];
    const float* bq   = (const float*)d_in[8];
    const float* wk   = (const float*)d_in[9];
    const float* bk   = (const float*)d_in[10];
    const float* wv   = (const float*)d_in[11];
    const float* bv   = (const float*)d_in[12];
    const float* wo   = (const float*)d_in[13];
    const float* bo   = (const float*)d_in[14];

    float* G = (float*)d_out;
    float* A = G + (size_t)BB * CC * LL;   // outputs concatenated: G then A_flat

    gating_kernel<<<NBLK, 192>>>(x, gc_w, gc_b, w1, b1, w2, b2);
    meantopk_kernel<<<1, 1024>>>(wq, bq, wk, bk, wv, bv, wo, bo);
    attn_kernel<<<BB / AB, 128>>>(x, G, A);
}